// round 16
// baseline (speedup 1.0000x reference)
#include <cuda_runtime.h>
#include <cuda_fp16.h>
#include <math.h>
#include <stdint.h>

// Problem constants
#define BB 2
#define TT 2048
#define DM 2048
#define NH 16
#define HD 128
#define NKV 4
#define NREP 4
#define HALF 64
#define MTOT (BB*TT)      // 4096
#define QN (NH*HD)        // 2048
#define KN (NKV*HD)       // 512

// Scratch (device globals: no allocations allowed)
__device__ float  g_q[MTOT * QN];      // 32 MB  Q proj out (fp32)
__device__ float  g_k[MTOT * KN];      //  8 MB  K proj out (fp32)
__device__ float  g_v[MTOT * KN];      //  8 MB  V proj out (fp32)
__device__ __half g_qh[MTOT * QN];     // 16 MB  rope(Q) fp16
__device__ __half g_kh[MTOT * KN];     //  4 MB  rope(K) fp16
__device__ __half g_ah[MTOT * QN];     // 16 MB  attention out fp16
__device__ __half g_xh[MTOT * DM];     // 16 MB  x as fp16
__device__ __half g_wqT[DM * QN];      //  8 MB  transposed fp16 weights [N][K]
__device__ __half g_wkT[DM * KN];      //  2 MB
__device__ __half g_wvT[DM * KN];      //  2 MB
__device__ __half g_woT[DM * DM];      //  8 MB
__device__ __half g_vt[(size_t)BB * NKV * HD * TT];  // 4 MB V^T fp16 (b,kv,d,t)

// ---------------------------------------------------------------------------
// MMA helpers (fp16, f32 accumulate)
// ---------------------------------------------------------------------------
__device__ __forceinline__ void mma_fp16(float* d, const uint32_t* a,
                                         uint32_t b0, uint32_t b1) {
    asm volatile(
        "mma.sync.aligned.m16n8k16.row.col.f32.f16.f16.f32 "
        "{%0,%1,%2,%3}, {%4,%5,%6,%7}, {%8,%9}, {%0,%1,%2,%3};\n"
        : "+f"(d[0]), "+f"(d[1]), "+f"(d[2]), "+f"(d[3])
        : "r"(a[0]), "r"(a[1]), "r"(a[2]), "r"(a[3]),
          "r"(b0), "r"(b1));
}

// ---------------------------------------------------------------------------
// Elementwise fp32 -> fp16
// ---------------------------------------------------------------------------
__global__ void cvt_fp16_kernel(const float4* __restrict__ src,
                                uint2* __restrict__ dst, int n4)
{
    int i = blockIdx.x * blockDim.x + threadIdx.x;
    if (i >= n4) return;
    float4 v = src[i];
    __half2 lo = __floats2half2_rn(v.x, v.y);
    __half2 hi = __floats2half2_rn(v.z, v.w);
    dst[i] = make_uint2(*(uint32_t*)&lo, *(uint32_t*)&hi);
}

// ---------------------------------------------------------------------------
// Weight transpose + fp16 convert: src [R][C] fp32 -> dst [C][R] fp16
// ---------------------------------------------------------------------------
__global__ void transpose_kernel(const float* __restrict__ src,
                                 __half* __restrict__ dst, int R, int C)
{
    __shared__ float t[32][33];
    int c0 = blockIdx.x * 32, r0 = blockIdx.y * 32;
    int x = threadIdx.x, y = threadIdx.y;   // block (32, 8)
#pragma unroll
    for (int i = 0; i < 32; i += 8)
        t[y + i][x] = src[(size_t)(r0 + y + i) * C + c0 + x];
    __syncthreads();
#pragma unroll
    for (int i = 0; i < 32; i += 8)
        dst[(size_t)(c0 + y + i) * R + r0 + x] = __float2half(t[x][y + i]);
}

// ---------------------------------------------------------------------------
// V fp32 (b,t,kv,d) -> V^T fp16 (b,kv,d,t)
// ---------------------------------------------------------------------------
__global__ void v_to_half_t_kernel(const float* __restrict__ v,
                                   __half* __restrict__ vt)
{
    __shared__ float t[32][33];
    int t0 = blockIdx.x * 32;
    int d0 = blockIdx.y * 32;
    int bk = blockIdx.z;
    int b = bk >> 2, kv = bk & 3;
    int x = threadIdx.x, y = threadIdx.y;   // (32, 8)
    const float* src = v + ((size_t)b * TT) * KN + kv * HD;
#pragma unroll
    for (int i = 0; i < 32; i += 8)
        t[y + i][x] = src[(size_t)(t0 + y + i) * KN + d0 + x];
    __syncthreads();
    __half* dst = vt + ((size_t)bk * HD + d0) * TT + t0;
#pragma unroll
    for (int i = 0; i < 32; i += 8)
        dst[(size_t)(y + i) * TT + x] = __float2half(t[x][y + i]);
}

// ---------------------------------------------------------------------------
// FP16 tensor-core GEMM: C[M,N] = A[M,K] @ B[K,N], fp32 out.
// A and Bt supplied as fp16 viewed as half2 WORDS; Kw = K/2 is the word count.
// Word-level fragment layout of m16n8k16.f16 == m16n8k8.tf32, so this is the
// validated R8 body with the MMA swapped. CTA tile 256x128 (elements),
// chunk = 16 words = 32 k-elements, 8 warps (4x2), warp tile 64x64.
// ---------------------------------------------------------------------------
#define GBM 256
#define GBN 128
#define GBKW 16   // words per chunk (= 32 halves)

__device__ __forceinline__ void gemm_body(
    const uint32_t* __restrict__ A, const uint32_t* __restrict__ Bt,
    float* __restrict__ C, int M, int N, int Kw)
{
    __shared__ __align__(16) uint32_t As[GBM * GBKW];
    __shared__ __align__(16) uint32_t Bs[GBN * GBKW];

    const int tid  = threadIdx.x;
    const int lane = tid & 31;
    const int warp = tid >> 5;
    const int gid  = lane >> 2;
    const int tig  = lane & 3;
    const int wy   = warp >> 1;
    const int wx   = warp & 1;
    const int m0   = blockIdx.y * GBM;
    const int n0   = blockIdx.x * GBN;

    const int c4    = tid & 3;
    const int rbase = tid >> 2;
    const int ksS   = c4 >> 1;
    const int khS   = c4 & 1;

    const uint32_t* Ag = A  + (size_t)(m0 + rbase) * Kw + c4 * 4;
    const uint32_t* Bg = Bt + (size_t)(n0 + rbase) * Kw + c4 * 4;

    float acc[4][8][4];
#pragma unroll
    for (int mt = 0; mt < 4; mt++)
#pragma unroll
        for (int nt = 0; nt < 8; nt++)
#pragma unroll
            for (int r = 0; r < 4; r++) acc[mt][nt][r] = 0.0f;

    uint4 pa[4], pb[2];
    const int NC = Kw / GBKW;

#pragma unroll
    for (int i = 0; i < 4; i++)
        pa[i] = *(const uint4*)&Ag[(size_t)(64 * i) * Kw];
#pragma unroll
    for (int i = 0; i < 2; i++)
        pb[i] = *(const uint4*)&Bg[(size_t)(64 * i) * Kw];

    {
#pragma unroll
        for (int i = 0; i < 4; i++) {
            int r  = rbase + 64 * i;
            int Mi = r >> 4, g = r & 7, rh = (r >> 3) & 1;
            int base = ((Mi * 2 + ksS) * 32 + g * 4);
            int roff = rh + 2 * khS;
            uint32_t e[4] = {pa[i].x, pa[i].y, pa[i].z, pa[i].w};
#pragma unroll
            for (int jj = 0; jj < 4; jj++) {
                int j = (jj + c4 + g) & 3;
                As[(base + j) * 4 + roff] = e[j];
            }
        }
#pragma unroll
        for (int i = 0; i < 2; i++) {
            int r  = rbase + 64 * i;
            int Ni = r >> 3, g = r & 7;
            int base = ((Ni * 2 + ksS) * 32 + g * 4);
            uint32_t e[4] = {pb[i].x, pb[i].y, pb[i].z, pb[i].w};
#pragma unroll
            for (int jj = 0; jj < 4; jj++) {
                int j = (jj + c4 + g) & 3;
                Bs[(base + j) * 2 + khS] = e[j];
            }
        }
    }
    __syncthreads();

    for (int kc = 0; kc < NC; kc++) {
        if (kc + 1 < NC) {
            size_t koff = (size_t)(kc + 1) * GBKW;
#pragma unroll
            for (int i = 0; i < 4; i++)
                pa[i] = *(const uint4*)&Ag[(size_t)(64 * i) * Kw + koff];
#pragma unroll
            for (int i = 0; i < 2; i++)
                pb[i] = *(const uint4*)&Bg[(size_t)(64 * i) * Kw + koff];
        }

#pragma unroll
        for (int ks = 0; ks < 2; ks++) {
            uint32_t a[4][4], b[8][2];
#pragma unroll
            for (int mt = 0; mt < 4; mt++) {
                int Mi = wy * 4 + mt;
                uint4 v = *(const uint4*)&As[((Mi * 2 + ks) * 32 + lane) * 4];
                a[mt][0] = v.x; a[mt][1] = v.y; a[mt][2] = v.z; a[mt][3] = v.w;
            }
#pragma unroll
            for (int nt = 0; nt < 8; nt++) {
                int Ni = wx * 8 + nt;
                uint2 v = *(const uint2*)&Bs[((Ni * 2 + ks) * 32 + lane) * 2];
                b[nt][0] = v.x; b[nt][1] = v.y;
            }
#pragma unroll
            for (int mt = 0; mt < 4; mt++)
#pragma unroll
                for (int nt = 0; nt < 8; nt++)
                    mma_fp16(acc[mt][nt], a[mt], b[nt][0], b[nt][1]);
        }

        if (kc + 1 < NC) {
            __syncthreads();
#pragma unroll
            for (int i = 0; i < 4; i++) {
                int r  = rbase + 64 * i;
                int Mi = r >> 4, g = r & 7, rh = (r >> 3) & 1;
                int base = ((Mi * 2 + ksS) * 32 + g * 4);
                int roff = rh + 2 * khS;
                uint32_t e[4] = {pa[i].x, pa[i].y, pa[i].z, pa[i].w};
#pragma unroll
                for (int jj = 0; jj < 4; jj++) {
                    int j = (jj + c4 + g) & 3;
                    As[(base + j) * 4 + roff] = e[j];
                }
            }
#pragma unroll
            for (int i = 0; i < 2; i++) {
                int r  = rbase + 64 * i;
                int Ni = r >> 3, g = r & 7;
                int base = ((Ni * 2 + ksS) * 32 + g * 4);
                uint32_t e[4] = {pb[i].x, pb[i].y, pb[i].z, pb[i].w};
#pragma unroll
                for (int jj = 0; jj < 4; jj++) {
                    int j = (jj + c4 + g) & 3;
                    Bs[(base + j) * 2 + khS] = e[j];
                }
            }
            __syncthreads();
        }
    }

#pragma unroll
    for (int mt = 0; mt < 4; mt++) {
        int row = m0 + wy * 64 + mt * 16 + gid;
#pragma unroll
        for (int nt = 0; nt < 8; nt++) {
            int col = n0 + wx * 64 + nt * 8 + tig * 2;
            float2 lo = {acc[mt][nt][0], acc[mt][nt][1]};
            float2 hi = {acc[mt][nt][2], acc[mt][nt][3]};
            *(float2*)&C[(size_t)row * N + col]       = lo;
            *(float2*)&C[(size_t)(row + 8) * N + col] = hi;
        }
    }
}

__global__ __launch_bounds__(256, 1) void gemm_h(
    const uint32_t* __restrict__ A, const uint32_t* __restrict__ Bt,
    float* __restrict__ C, int M, int N, int Kw)
{
    gemm_body(A, Bt, C, M, N, Kw);
}

__global__ __launch_bounds__(256, 1) void gemm_h_kv(
    const uint32_t* __restrict__ A,
    const uint32_t* __restrict__ BtK, const uint32_t* __restrict__ BtV,
    float* __restrict__ Ck, float* __restrict__ Cv, int M, int N, int Kw)
{
    const uint32_t* Bt = blockIdx.z ? BtV : BtK;
    float* C = blockIdx.z ? Cv : Ck;
    gemm_body(A, Bt, C, M, N, Kw);
}

// ---------------------------------------------------------------------------
// RoPE: read fp32 (b,t,heads,HD), rotate, scale, write fp16.
// ---------------------------------------------------------------------------
__global__ void rope_h_kernel(const float* __restrict__ q,
                              __half* __restrict__ qh,
                              const float* __restrict__ cosp,
                              const float* __restrict__ sinp,
                              int heads, float sc)
{
    int idx = blockIdx.x * blockDim.x + threadIdx.x;
    int total = BB * TT * heads * HALF;
    if (idx >= total) return;
    int i = idx % HALF;
    int h = (idx / HALF) % heads;
    int t = (idx / (HALF * heads)) % TT;
    int b = idx / (HALF * heads * TT);
    float c = cosp[t * HALF + i];
    float s = sinp[t * HALF + i];
    size_t base = (((size_t)b * TT + t) * heads + h) * HD;
    float x1 = q[base + i];
    float x2 = q[base + i + HALF];
    qh[base + i]        = __float2half((x1 * c - x2 * s) * sc);
    qh[base + i + HALF] = __float2half((x2 * c + x1 * s) * sc);
}

// ---------------------------------------------------------------------------
// FP16 tensor-core causal GQA flash attention.
// S = QK^T via m16n8k16.f16 (Q pre-scaled), softmax in registers,
// P in registers as fp16 A-frags, O += P@V via m16n8k16.f16.
// CTA: 128 q rows, key tiles of 64, 8 warps, warp owns 16 rows.
// Smem (words): Qs[128][68] half2, Ks[64][68] half2, Vw[128][36] half2.
// ---------------------------------------------------------------------------
#define AQS 68
#define AVS 36
#define ATTN_SMEM_BYTES ((128*AQS + 64*AQS + 128*AVS) * 4)   // 70656

__global__ __launch_bounds__(256, 1) void attn_mma_kernel(
    const __half* __restrict__ Qh, const __half* __restrict__ Kh,
    const __half* __restrict__ Vt, __half* __restrict__ Oh)
{
    extern __shared__ uint32_t smw[];
    uint32_t* Qs = smw;                  // [128][68] half2 words
    uint32_t* Ks = Qs + 128 * AQS;       // [64][68]
    uint32_t* Vw = Ks + 64 * AQS;        // [128][36] (V^T key-pairs)

    const int tid  = threadIdx.x;
    const int lane = tid & 31;
    const int warp = tid >> 5;
    const int gid  = lane >> 2;
    const int tig  = lane & 3;
    const int qt   = (gridDim.x - 1) - blockIdx.x;   // long CTAs first
    const int h    = blockIdx.y;
    const int b    = blockIdx.z;
    const int kvh  = h >> 2;
    const int qi0  = qt * 128;

    // ---- stage Q (half2 word copy; already scaled) ----
    const uint32_t* qbase = (const uint32_t*)Qh
        + (((size_t)b * TT + qi0) * NH + h) * (HD / 2);
#pragma unroll
    for (int i = 0; i < 8; i++) {
        int idx = tid + i * 256;        // 0..2047
        int r = idx >> 4, d4 = idx & 15;
        *(uint4*)&Qs[r * AQS + d4 * 4] =
            *(const uint4*)&qbase[(size_t)r * (QN / 2) + d4 * 4];
    }

    float m_i[2] = {-1e30f, -1e30f};
    float l_i[2] = {0.0f, 0.0f};
    float o[16][4];
#pragma unroll
    for (int nt = 0; nt < 16; nt++)
#pragma unroll
        for (int r = 0; r < 4; r++) o[nt][r] = 0.0f;

    const int arow = warp * 16 + gid;
    const int ntiles = qi0 / 64 + 2;
    const __half* vth = Vt + ((size_t)(b * NKV + kvh) * HD) * TT;

    for (int kt = 0; kt < ntiles; kt++) {
        const int kj0 = kt * 64;
        __syncthreads();

        // ---- stage K (half2 word copy) ----
        const uint32_t* kbase = (const uint32_t*)Kh
            + (((size_t)b * TT + kj0) * NKV + kvh) * (HD / 2);
#pragma unroll
        for (int i = 0; i < 4; i++) {
            int idx = tid + i * 256;    // 0..1023
            int r = idx >> 4, d4 = idx & 15;
            *(uint4*)&Ks[r * AQS + d4 * 4] =
                *(const uint4*)&kbase[(size_t)r * (KN / 2) + d4 * 4];
        }
        // ---- stage V^T (half2 copy) ----
#pragma unroll
        for (int i = 0; i < 16; i++) {
            int idx = i * 256 + tid;
            int kp = idx & 31, d = idx >> 5;
            Vw[d * AVS + kp] =
                *(const uint32_t*)&vth[(size_t)d * TT + kj0 + 2 * kp];
        }
        __syncthreads();

        // ---- S = Q K^T (fp16 mma, warp tile 16x64, 8 k16-steps) ----
        float s[8][4];
#pragma unroll
        for (int nt = 0; nt < 8; nt++)
#pragma unroll
            for (int r = 0; r < 4; r++) s[nt][r] = 0.0f;

#pragma unroll
        for (int ks = 0; ks < 8; ks++) {
            uint32_t a[4];
            int ab = arow * AQS + ks * 8 + tig;
            a[0] = Qs[ab];
            a[1] = Qs[ab + 8 * AQS];
            a[2] = Qs[ab + 4];
            a[3] = Qs[ab + 8 * AQS + 4];
#pragma unroll
            for (int nt = 0; nt < 8; nt++) {
                int kb = (nt * 8 + gid) * AQS + ks * 8 + tig;
                mma_fp16(s[nt], a, Ks[kb], Ks[kb + 4]);
            }
        }

        // ---- causal mask ----
        if (kt >= ntiles - 2) {
#pragma unroll
            for (int nt = 0; nt < 8; nt++)
#pragma unroll
                for (int r = 0; r < 4; r++) {
                    int row = qi0 + warp * 16 + gid + (r >> 1) * 8;
                    int col = kj0 + nt * 8 + 2 * tig + (r & 1);
                    if (col > row) s[nt][r] = -1e30f;
                }
        }

        // ---- online softmax ----
        uint32_t ph[8][2];
#pragma unroll
        for (int e = 0; e < 2; e++) {
            float mx = -1e30f;
#pragma unroll
            for (int nt = 0; nt < 8; nt++)
                mx = fmaxf(mx, fmaxf(s[nt][2 * e], s[nt][2 * e + 1]));
            mx = fmaxf(mx, __shfl_xor_sync(0xffffffffu, mx, 1));
            mx = fmaxf(mx, __shfl_xor_sync(0xffffffffu, mx, 2));
            float mnew = fmaxf(m_i[e], mx);
            float corr = __expf(m_i[e] - mnew);
            m_i[e] = mnew;
            float rsum = 0.0f;
#pragma unroll
            for (int nt = 0; nt < 8; nt++) {
                float p0 = __expf(s[nt][2 * e]     - mnew);
                float p1 = __expf(s[nt][2 * e + 1] - mnew);
                rsum += p0 + p1;
                __half2 hp = __floats2half2_rn(p0, p1);
                ph[nt][e] = *(uint32_t*)&hp;
            }
            rsum += __shfl_xor_sync(0xffffffffu, rsum, 1);
            rsum += __shfl_xor_sync(0xffffffffu, rsum, 2);
            l_i[e] = l_i[e] * corr + rsum;
#pragma unroll
            for (int nt = 0; nt < 16; nt++) {
                o[nt][2 * e]     *= corr;
                o[nt][2 * e + 1] *= corr;
            }
        }

        // ---- O += P @ V (fp16 mma) ----
#pragma unroll
        for (int ks = 0; ks < 4; ks++) {
            uint32_t a[4] = { ph[2 * ks][0], ph[2 * ks][1],
                              ph[2 * ks + 1][0], ph[2 * ks + 1][1] };
#pragma unroll
            for (int nt = 0; nt < 16; nt++) {
                int vb = (nt * 8 + gid) * AVS + ks * 8 + tig;
                mma_fp16(o[nt], a, Vw[vb], Vw[vb + 4]);
            }
        }
    }

    // ---- epilogue: normalize, write fp16 (feeds O-proj GEMM) ----
    __half* obase = Oh + (((size_t)b * TT + qi0 + warp * 16) * NH + h) * HD;
    float inv0 = 1.0f / l_i[0];
    float inv1 = 1.0f / l_i[1];
#pragma unroll
    for (int nt = 0; nt < 16; nt++) {
        __half2 v0 = __floats2half2_rn(o[nt][0] * inv0, o[nt][1] * inv0);
        __half2 v1 = __floats2half2_rn(o[nt][2] * inv1, o[nt][3] * inv1);
        *(__half2*)&obase[(size_t)gid * QN + nt * 8 + 2 * tig]       = v0;
        *(__half2*)&obase[(size_t)(gid + 8) * QN + nt * 8 + 2 * tig] = v1;
    }
}

// ---------------------------------------------------------------------------
// Launch
// ---------------------------------------------------------------------------
extern "C" void kernel_launch(void* const* d_in, const int* in_sizes, int n_in,
                              void* d_out, int out_size)
{
    const float* x    = (const float*)d_in[0];
    const float* wq   = (const float*)d_in[1];
    const float* wk   = (const float*)d_in[2];
    const float* wv   = (const float*)d_in[3];
    const float* wo   = (const float*)d_in[4];
    const float* cosp = (const float*)d_in[5];
    const float* sinp = (const float*)d_in[6];
    float* out = (float*)d_out;

    float *qp, *kp, *vp;
    __half *qh, *kh, *ah, *xh, *wqT, *wkT, *wvT, *woT, *vt;
    cudaGetSymbolAddress((void**)&qp,  g_q);
    cudaGetSymbolAddress((void**)&kp,  g_k);
    cudaGetSymbolAddress((void**)&vp,  g_v);
    cudaGetSymbolAddress((void**)&qh,  g_qh);
    cudaGetSymbolAddress((void**)&kh,  g_kh);
    cudaGetSymbolAddress((void**)&ah,  g_ah);
    cudaGetSymbolAddress((void**)&xh,  g_xh);
    cudaGetSymbolAddress((void**)&wqT, g_wqT);
    cudaGetSymbolAddress((void**)&wkT, g_wkT);
    cudaGetSymbolAddress((void**)&wvT, g_wvT);
    cudaGetSymbolAddress((void**)&woT, g_woT);
    cudaGetSymbolAddress((void**)&vt,  g_vt);

    cudaFuncSetAttribute(attn_mma_kernel,
                         cudaFuncAttributeMaxDynamicSharedMemorySize,
                         ATTN_SMEM_BYTES);

    const float scale = 0.08838834764831845f;  // 1/sqrt(128)
    const int KW = DM / 2;                      // K in half2 words

    // x -> fp16 once
    {
        int n4 = MTOT * DM / 4;
        cvt_fp16_kernel<<<(n4 + 255) / 256, 256>>>(
            (const float4*)x, (uint2*)xh, n4);
    }

    // Transpose+convert weights to [N][K] fp16
    dim3 tb(32, 8);
    transpose_kernel<<<dim3(QN / 32, DM / 32), tb>>>(wq, wqT, DM, QN);
    transpose_kernel<<<dim3(KN / 32, DM / 32), tb>>>(wk, wkT, DM, KN);
    transpose_kernel<<<dim3(KN / 32, DM / 32), tb>>>(wv, wvT, DM, KN);
    transpose_kernel<<<dim3(QN / 32, DM / 32), tb>>>(wo, woT, DM, DM);

    // QKV projections (fp16 tensor cores, fp32 out)
    gemm_h<<<dim3(QN / GBN, MTOT / GBM), 256>>>(
        (const uint32_t*)xh, (const uint32_t*)wqT, qp, MTOT, QN, KW);
    gemm_h_kv<<<dim3(KN / GBN, MTOT / GBM, 2), 256>>>(
        (const uint32_t*)xh, (const uint32_t*)wkT, (const uint32_t*)wvT,
        kp, vp, MTOT, KN, KW);

    // RoPE fp32 -> fp16 (Q gets 1/sqrt(d) folded in)
    {
        int tq = BB * TT * NH * HALF;
        rope_h_kernel<<<(tq + 255) / 256, 256>>>(qp, qh, cosp, sinp, NH, scale);
        int tk = BB * TT * NKV * HALF;
        rope_h_kernel<<<(tk + 255) / 256, 256>>>(kp, kh, cosp, sinp, NKV, 1.0f);
    }

    // V -> fp16 transposed (b,kv,d,t)
    v_to_half_t_kernel<<<dim3(TT / 32, HD / 32, BB * NKV), tb>>>(vp, vt);

    // Flash attention (fp16 tensor cores)
    attn_mma_kernel<<<dim3(TT / 128, NH, BB), 256, ATTN_SMEM_BYTES>>>(
        qh, kh, vt, ah);

    // Output projection (fp16 tensor cores, fp32 out)
    gemm_h<<<dim3(QN / GBN, MTOT / GBM), 256>>>(
        (const uint32_t*)ah, (const uint32_t*)woT, out, MTOT, QN, KW);
}